// round 13
// baseline (speedup 1.0000x reference)
#include <cuda_runtime.h>
#include <cuda_fp16.h>

// Problem constants
#define NNODE   10000
#define NEDGE   160000
#define FIN     3703
#define KPAD    3712     // FIN padded to multiple of 16
#define DMODEL  256
#define NHEAD   32
#define DK      16
#define QKV     512
#define QKV3    1536
#define NLAYER  7

// GEMM tiling (R10-proven skeleton)
#define BM 128
#define BN 128
#define SROWH 24
#define TILE_H (128*SROWH)
#define STAGE_H (4*TILE_H)
#define WSCALE 32.0f
#define WINV   0.03125f

#define SQ1 (QKV*DMODEL)
#define SQT (NLAYER*SQ1)
#define SOT (NLAYER*DMODEL*QKV)
#define SMT (NLAYER*DMODEL*DMODEL)
#define WTOT (3*SQT + SOT + SMT)

// ---------------- device scratch ----------------
__device__ __half g_xh [NNODE * KPAD];
__device__ __half g_xl [NNODE * KPAD];
__device__ __half g_Weh[DMODEL * KPAD];
__device__ __half g_Wel[DMODEL * KPAD];
__device__ __half g_Wfh[NLAYER * QKV3 * DMODEL];
__device__ __half g_Wfl[NLAYER * QKV3 * DMODEL];
__device__ __half g_Woh[SOT];
__device__ __half g_Wol[SOT];
__device__ __half g_Wmh[SMT];
__device__ __half g_Wml[SMT];

__device__ float  g_h  [NNODE * DMODEL];
__device__ __half g_hh [NNODE * DMODEL];
__device__ __half g_hl [NNODE * DMODEL];
__device__ float  g_t0 [NNODE * DMODEL];
__device__ float  g_t1 [NNODE * DMODEL];
__device__ __half g_t1h[NNODE * DMODEL];
__device__ __half g_t1l[NNODE * DMODEL];
__device__ __half g_QKVh[NNODE * QKV3];   // remapped: Q[a][h] | K[b][h] | V[h][b]
__device__ __half g_QKVl[NNODE * QKV3];
__device__ __half g_ath[NNODE * QKV];
__device__ __half g_atl[NNODE * QKV];

__device__ int g_cnt [NNODE];
__device__ int g_off [NNODE + 1];
__device__ int g_cur [NNODE];
__device__ int g_esrc[NEDGE];
__device__ int g_is64;

// ---------------- fp16 two-term split ----------------
__device__ __forceinline__ void splith(float x, __half& hi, __half& lo) {
    hi = __float2half_rn(x);
    lo = __float2half_rn(x - __half2float(hi));
}
__device__ __forceinline__ unsigned h2pack(__half a, __half b) {
    __half2 t = __halves2half2(a, b);
    return *(unsigned*)&t;
}

// ---------------- split kernels ----------------
__global__ void split_pad_kernel(const float* __restrict__ src,
                                 __half* __restrict__ hi, __half* __restrict__ lo,
                                 int cols, int colspad, float scale) {
    int row = blockIdx.x;
    const float* s = src + (size_t)row * cols;
    __half* ph = hi + (size_t)row * colspad;
    __half* pl = lo + (size_t)row * colspad;
    for (int c = threadIdx.x; c < cols; c += blockDim.x) {
        __half h, l;
        splith(s[c] * scale, h, l);
        ph[c] = h; pl[c] = l;
    }
}

__global__ void splitw_kernel(const float* __restrict__ Wq, const float* __restrict__ Wk,
                              const float* __restrict__ Wv, const float* __restrict__ Wo,
                              const float* __restrict__ Wm) {
    int idx = blockIdx.x * blockDim.x + threadIdx.x;
    if (idx >= WTOT) return;
    float v; __half *dh, *dl;
    if (idx < SQT) {
        int l = idx / SQ1, r = idx % SQ1;
        v = Wq[idx]; int d = l * (3 * SQ1) + r;
        dh = g_Wfh + d; dl = g_Wfl + d;
    } else if (idx < 2 * SQT) {
        int i2 = idx - SQT;
        int l = i2 / SQ1, r = i2 % SQ1;
        v = Wk[i2]; int d = l * (3 * SQ1) + SQ1 + r;
        dh = g_Wfh + d; dl = g_Wfl + d;
    } else if (idx < 3 * SQT) {
        int i2 = idx - 2 * SQT;
        int l = i2 / SQ1, r = i2 % SQ1;
        v = Wv[i2]; int d = l * (3 * SQ1) + 2 * SQ1 + r;
        dh = g_Wfh + d; dl = g_Wfl + d;
    } else if (idx < 3 * SQT + SOT) {
        int i2 = idx - 3 * SQT;
        v = Wo[i2]; dh = g_Woh + i2; dl = g_Wol + i2;
    } else {
        int i2 = idx - 3 * SQT - SOT;
        v = Wm[i2]; dh = g_Wmh + i2; dl = g_Wml + i2;
    }
    __half h, l;
    splith(v * WSCALE, h, l);
    *dh = h; *dl = l;
}

// ---------------- edge index dtype detection + CSR ----------------
__global__ void detect_kernel(const unsigned int* __restrict__ w) {
    if (threadIdx.x == 0 && blockIdx.x == 0) {
        int is64 = 1;
        for (int i = 1; i < 128; i += 2)
            if (w[i] != 0u) { is64 = 0; break; }
        g_is64 = is64;
    }
}

__device__ __forceinline__ int read_edge(const void* eidx, int pos) {
    if (g_is64) return (int)(((const long long*)eidx)[pos]);
    return ((const int*)eidx)[pos];
}

__global__ void zero_cnt_kernel() {
    int i = blockIdx.x * blockDim.x + threadIdx.x;
    if (i < NNODE) g_cnt[i] = 0;
}

__global__ void hist_kernel(const void* __restrict__ eidx) {
    int e = blockIdx.x * blockDim.x + threadIdx.x;
    if (e >= NEDGE) return;
    atomicAdd(&g_cnt[read_edge(eidx, NEDGE + e)], 1);
}

__global__ void scan_kernel() {
    __shared__ int ss[1024];
    int t = threadIdx.x;
    const int CH = (NNODE + 1023) / 1024;
    int b = t * CH;
    int e = b + CH; if (e > NNODE) e = NNODE;
    int s = 0;
    for (int i = b; i < e; i++) s += g_cnt[i];
    ss[t] = s;
    __syncthreads();
    for (int o = 1; o < 1024; o <<= 1) {
        int v = (t >= o) ? ss[t - o] : 0;
        __syncthreads();
        ss[t] += v;
        __syncthreads();
    }
    int base = ss[t] - s;
    for (int i = b; i < e; i++) {
        g_off[i] = base;
        g_cur[i] = base;
        base += g_cnt[i];
    }
    if (t == 1023) g_off[NNODE] = ss[1023];
}

__global__ void scatter_kernel(const void* __restrict__ eidx) {
    int e = blockIdx.x * blockDim.x + threadIdx.x;
    if (e >= NEDGE) return;
    int d = read_edge(eidx, NEDGE + e);
    int s = read_edge(eidx, e);
    g_esrc[atomicAdd(&g_cur[d], 1)] = s;
}

// ---------------- fp16 mma + ldmatrix helpers ----------------
__device__ __forceinline__ void mma16(float* c,
                                      unsigned a0, unsigned a1, unsigned a2, unsigned a3,
                                      unsigned b0, unsigned b1) {
    asm volatile(
        "mma.sync.aligned.m16n8k16.row.col.f32.f16.f16.f32 "
        "{%0,%1,%2,%3}, {%4,%5,%6,%7}, {%8,%9}, {%0,%1,%2,%3};\n"
        : "+f"(c[0]), "+f"(c[1]), "+f"(c[2]), "+f"(c[3])
        : "r"(a0), "r"(a1), "r"(a2), "r"(a3), "r"(b0), "r"(b1));
}

__device__ __forceinline__ void ldsm4(unsigned& r0, unsigned& r1,
                                      unsigned& r2, unsigned& r3, unsigned addr) {
    asm volatile(
        "ldmatrix.sync.aligned.m8n8.x4.shared.b16 {%0,%1,%2,%3}, [%4];\n"
        : "=r"(r0), "=r"(r1), "=r"(r2), "=r"(r3) : "r"(addr));
}

// ---------------- GEMM: C = addend + bias + (A @ B^T)/32  (3xFP16) --------
// remap=1 (QKV gemm): skip fp32 C; write Ch/Cl with n remapped:
//   region r = n>>9, h = (n&511)>>4, b = n&15
//   r=0 (Q): n' = b*32 + h      (Q stored [a][h], a==b here)
//   r=1 (K): n' = 512 + b*32 + h  (K stored [b][h])
//   r=2 (V): n' = n               (V stays [h][b])
__global__ __launch_bounds__(256, 2)
void gemm3h(const __half* __restrict__ Ah, const __half* __restrict__ Al,
            const __half* __restrict__ Bh, const __half* __restrict__ Bl,
            const float* __restrict__ bias, const float* __restrict__ addend,
            float* __restrict__ C, __half* __restrict__ Ch, __half* __restrict__ Cl,
            int M, int Nn, int K, int remap)
{
    __shared__ __align__(16) __half smem[2][STAGE_H];   // 48 KB

    const int tid = threadIdx.x;
    const int m0 = blockIdx.y * BM;
    const int n0 = blockIdx.x * BN;
    const int lane = tid & 31, wid = tid >> 5;
    const int wm = wid & 1, wn = wid >> 1;

    const int nkt = K >> 4;

    float acc[4][4][4] = {};

    const int lr = tid >> 1;
    const int lc = (tid & 1) * 8;
    const int mA = (m0 + lr < M) ? (m0 + lr) : (M - 1);
    const int nB = n0 + lr;

    const int a_row = ((lane >> 3) & 1) * 8 + (lane & 7);
    const int a_col = ((lane >> 4) & 1) * 8;
    const unsigned aoffB = (unsigned)((a_row * SROWH + a_col) * 2);
    const int b_row = ((lane >> 4) & 1) * 8 + (lane & 7);
    const int b_col = ((lane >> 3) & 1) * 8;
    const unsigned boffB = (unsigned)((b_row * SROWH + b_col) * 2);

    unsigned sbase[2];
    sbase[0] = (unsigned)__cvta_generic_to_shared(&smem[0][0]);
    sbase[1] = (unsigned)__cvta_generic_to_shared(&smem[1][0]);

    uint4 vah, val, vbh, vbl;

#define LOADT(t_) do {                                                         \
        const int _k16 = (t_) << 4;                                           \
        vah = *(const uint4*)(Ah + (size_t)mA * K + _k16 + lc);                \
        val = *(const uint4*)(Al + (size_t)mA * K + _k16 + lc);                \
        vbh = *(const uint4*)(Bh + (size_t)nB * K + _k16 + lc);                \
        vbl = *(const uint4*)(Bl + (size_t)nB * K + _k16 + lc);                \
    } while (0)

#define STORET(st_) do {                                                       \
        __half* _s = smem[st_];                                                \
        *(uint4*)&_s[             lr * SROWH + lc] = vah;                      \
        *(uint4*)&_s[TILE_H     + lr * SROWH + lc] = val;                      \
        *(uint4*)&_s[2 * TILE_H + lr * SROWH + lc] = vbh;                      \
        *(uint4*)&_s[3 * TILE_H + lr * SROWH + lc] = vbl;                      \
    } while (0)

    LOADT(0);
    STORET(0);
    __syncthreads();

    for (int t = 0; t < nkt; t++) {
        const int cur = t & 1;
        if (t + 1 < nkt) LOADT(t + 1);

        const unsigned sb = sbase[cur];

        unsigned bh0[4], bh1[4], bl0[4], bl1[4];
#pragma unroll
        for (int jp = 0; jp < 2; jp++) {
            unsigned bd = sb + (unsigned)((2 * TILE_H + (wn * 32 + jp * 16) * SROWH) * 2) + boffB;
            ldsm4(bh0[2 * jp], bh1[2 * jp], bh0[2 * jp + 1], bh1[2 * jp + 1], bd);
            ldsm4(bl0[2 * jp], bl1[2 * jp], bl0[2 * jp + 1], bl1[2 * jp + 1],
                  bd + (unsigned)(TILE_H * 2));
        }
#pragma unroll
        for (int i = 0; i < 4; i++) {
            unsigned ad = sb + (unsigned)(((wm * 64 + i * 16) * SROWH) * 2) + aoffB;
            unsigned ah0, ah1, ah2, ah3, al0, al1, al2, al3;
            ldsm4(ah0, ah1, ah2, ah3, ad);
            ldsm4(al0, al1, al2, al3, ad + (unsigned)(TILE_H * 2));
#pragma unroll
            for (int j = 0; j < 4; j++) {
                mma16(acc[i][j], ah0, ah1, ah2, ah3, bh0[j], bh1[j]);
                mma16(acc[i][j], al0, al1, al2, al3, bh0[j], bh1[j]);
                mma16(acc[i][j], ah0, ah1, ah2, ah3, bl0[j], bl1[j]);
            }
        }

        if (t + 1 < nkt) STORET(cur ^ 1);
        __syncthreads();
    }
#undef LOADT
#undef STORET

    // epilogue: rescale by 1/32
#pragma unroll
    for (int i = 0; i < 4; i++) {
        int mrow = m0 + wm * 64 + i * 16 + (lane >> 2);
#pragma unroll
        for (int j = 0; j < 4; j++) {
            int ncol = n0 + wn * 32 + j * 8 + (lane & 3) * 2;
            float bv0 = 0.f, bv1 = 0.f;
            if (bias) { bv0 = bias[ncol]; bv1 = bias[ncol + 1]; }
#pragma unroll
            for (int r = 0; r < 2; r++) {
                int mr = mrow + r * 8;
                if (mr >= M) continue;
                size_t idx = (size_t)mr * Nn + ncol;
                float v0 = acc[i][j][r * 2 + 0] * WINV + bv0;
                float v1 = acc[i][j][r * 2 + 1] * WINV + bv1;
                if (addend) { v0 += addend[idx]; v1 += addend[idx + 1]; }
                if (C) {
                    C[idx]     = v0;
                    C[idx + 1] = v1;
                }
                if (Ch) {
                    __half h0, l0, h1, l1;
                    splith(v0, h0, l0);
                    splith(v1, h1, l1);
                    if (!remap) {
                        Ch[idx] = h0;      Cl[idx] = l0;
                        Ch[idx + 1] = h1;  Cl[idx + 1] = l1;
                    } else {
                        int reg = ncol >> 9, local = ncol & 511;
                        int hh = local >> 4, bb = local & 15;
                        size_t base = (size_t)mr * Nn;
                        size_t np0, np1;
                        if (reg == 2) { np0 = base + ncol; np1 = np0 + 1; }
                        else {
                            np0 = base + (reg << 9) + bb * 32 + hh;
                            np1 = np0 + 32;   // ncol+1 -> b+1 (same h)
                        }
                        Ch[np0] = h0;  Cl[np0] = l0;
                        Ch[np1] = h1;  Cl[np1] = l1;
                    }
                }
            }
        }
    }
}

// ---------------- LayerNorm (warp per row) with optional split outputs ----
__global__ __launch_bounds__(256)
void ln_kernel(const float* __restrict__ X, const float* __restrict__ gamma,
               const float* __restrict__ beta, float* __restrict__ Y,
               __half* __restrict__ Yh, __half* __restrict__ Yl)
{
    int idx = blockIdx.x * blockDim.x + threadIdx.x;
    int row = idx >> 5;
    int lane = idx & 31;
    if (row >= NNODE) return;

    const float4* xp = (const float4*)(X + (size_t)row * DMODEL);
    float4 v0 = xp[lane];
    float4 v1 = xp[lane + 32];

    float s = v0.x + v0.y + v0.z + v0.w + v1.x + v1.y + v1.z + v1.w;
#pragma unroll
    for (int o = 16; o; o >>= 1) s += __shfl_xor_sync(0xffffffffu, s, o);
    float mean = s * (1.f / 256.f);

    float d, q = 0.f;
    d = v0.x - mean; q += d * d;  d = v0.y - mean; q += d * d;
    d = v0.z - mean; q += d * d;  d = v0.w - mean; q += d * d;
    d = v1.x - mean; q += d * d;  d = v1.y - mean; q += d * d;
    d = v1.z - mean; q += d * d;  d = v1.w - mean; q += d * d;
#pragma unroll
    for (int o = 16; o; o >>= 1) q += __shfl_xor_sync(0xffffffffu, q, o);
    float inv = rsqrtf(q * (1.f / 256.f) + 1e-5f);

    const float4* gp = (const float4*)gamma;
    const float4* bp = (const float4*)beta;
    float4 g0 = gp[lane], g1 = gp[lane + 32];
    float4 b0 = bp[lane], b1 = bp[lane + 32];

    float o0[4], o1[4];
    o0[0] = (v0.x - mean) * inv * g0.x + b0.x;
    o0[1] = (v0.y - mean) * inv * g0.y + b0.y;
    o0[2] = (v0.z - mean) * inv * g0.z + b0.z;
    o0[3] = (v0.w - mean) * inv * g0.w + b0.w;
    o1[0] = (v1.x - mean) * inv * g1.x + b1.x;
    o1[1] = (v1.y - mean) * inv * g1.y + b1.y;
    o1[2] = (v1.z - mean) * inv * g1.z + b1.z;
    o1[3] = (v1.w - mean) * inv * g1.w + b1.w;

    float4* yp = (float4*)(Y + (size_t)row * DMODEL);
    yp[lane]      = make_float4(o0[0], o0[1], o0[2], o0[3]);
    yp[lane + 32] = make_float4(o1[0], o1[1], o1[2], o1[3]);

    if (Yh) {
        __half hbuf0[4], lbuf0[4], hbuf1[4], lbuf1[4];
#pragma unroll
        for (int k = 0; k < 4; k++) {
            splith(o0[k], hbuf0[k], lbuf0[k]);
            splith(o1[k], hbuf1[k], lbuf1[k]);
        }
        uint2* hp = (uint2*)(Yh + (size_t)row * DMODEL);
        uint2* lp = (uint2*)(Yl + (size_t)row * DMODEL);
        hp[lane]      = *(uint2*)hbuf0;
        hp[lane + 32] = *(uint2*)hbuf1;
        lp[lane]      = *(uint2*)lbuf0;
        lp[lane + 32] = *(uint2*)lbuf1;
    }
}

// ---------------- edge attention: warp/node, tensor-core MMA --------------
// Remapped layouts (halves): Q at +0 as [a*32+h], K at +512 as [b*32+h],
// V at +1024 as [h*16+b]. All fragments per PTX m16n8k16 row.col:
//   A a0=(row g, k 2t,2t+1) a1=(row g+8) a2=(row g, k+8) a3=(row g+8, k+8)
//   B b0=(k 2t,2t+1, col g) b1=(k 2t+8,2t+9, col g)
//   C c0,c1=(row g, col 2t,2t+1) c2,c3=(row g+8)
__global__ __launch_bounds__(128)
void attn_mma_kernel(const __half* __restrict__ QKVh, const __half* __restrict__ QKVl,
                     __half* __restrict__ Omh, __half* __restrict__ Oml)
{
    const int warp = (blockIdx.x * blockDim.x + threadIdx.x) >> 5;
    const int lane = threadIdx.x & 31;
    if (warp >= NNODE) return;
    const int i = warp;
    const int g = lane >> 2;        // group row
    const int t = lane & 3;

    const __half* qH = QKVh + (size_t)i * QKV3;
    const __half* qL = QKVl + (size_t)i * QKV3;

    // Q A-fragments [kt(h-half)][a0..a3], hi & lo (Q stored [a*32+h])
    unsigned qh[2][4], ql[2][4];
#pragma unroll
    for (int kt = 0; kt < 2; kt++) {
        int k0 = kt * 16 + 2 * t;
        qh[kt][0] = *(const unsigned*)(qH + g * 32 + k0);
        qh[kt][1] = *(const unsigned*)(qH + (g + 8) * 32 + k0);
        qh[kt][2] = *(const unsigned*)(qH + g * 32 + k0 + 8);
        qh[kt][3] = *(const unsigned*)(qH + (g + 8) * 32 + k0 + 8);
        ql[kt][0] = *(const unsigned*)(qL + g * 32 + k0);
        ql[kt][1] = *(const unsigned*)(qL + (g + 8) * 32 + k0);
        ql[kt][2] = *(const unsigned*)(qL + g * 32 + k0 + 8);
        ql[kt][3] = *(const unsigned*)(qL + (g + 8) * 32 + k0 + 8);
    }

    float macc[4][4] = {};   // msg c-frags: 4 h-tiles of m16(a) x n8(h)

    const int e0 = g_off[i];
    const int e1 = g_off[i + 1];

    for (int e = e0; e < e1; e++) {
        const int j = g_esrc[e];
        const __half* kH = QKVh + (size_t)j * QKV3 + 512;
        const __half* kL = QKVl + (size_t)j * QKV3 + 512;
        const __half* vH = QKVh + (size_t)j * QKV3 + 1024;
        const __half* vL = QKVl + (size_t)j * QKV3 + 1024;

        // K B-frags [nt(b-half)][kt(h-half)][b0,b1]  (K stored [b*32+h])
        unsigned kh[2][2][2], kl[2][2][2];
#pragma unroll
        for (int nt = 0; nt < 2; nt++)
#pragma unroll
            for (int kt = 0; kt < 2; kt++) {
                int off = (nt * 8 + g) * 32 + kt * 16 + 2 * t;
                kh[nt][kt][0] = *(const unsigned*)(kH + off);
                kh[nt][kt][1] = *(const unsigned*)(kH + off + 8);
                kl[nt][kt][0] = *(const unsigned*)(kL + off);
                kl[nt][kt][1] = *(const unsigned*)(kL + off + 8);
            }
        // V B-frags [ht(h-tile)][b0,b1]  (V stored [h*16+b]; k=b)
        unsigned vh[4][2], vl[4][2];
#pragma unroll
        for (int ht = 0; ht < 4; ht++) {
            int off = (ht * 8 + g) * 16 + 2 * t;
            vh[ht][0] = *(const unsigned*)(vH + off);
            vh[ht][1] = *(const unsigned*)(vH + off + 8);
            vl[ht][0] = *(const unsigned*)(vL + off);
            vl[ht][1] = *(const unsigned*)(vL + off + 8);
        }

        // QK: alpha[a][b], 3 terms x 2 k-tiles per n-tile
        float cqk[2][4] = {};
#pragma unroll
        for (int nt = 0; nt < 2; nt++) {
#pragma unroll
            for (int kt = 0; kt < 2; kt++) {
                mma16(cqk[nt], qh[kt][0], qh[kt][1], qh[kt][2], qh[kt][3],
                      kh[nt][kt][0], kh[nt][kt][1]);
                mma16(cqk[nt], ql[kt][0], ql[kt][1], ql[kt][2], ql[kt][3],
                      kh[nt][kt][0], kh[nt][kt][1]);
                mma16(cqk[nt], qh[kt][0], qh[kt][1], qh[kt][2], qh[kt][3],
                      kl[nt][kt][0], kl[nt][kt][1]);
            }
        }

        // softmax over b (16 values per a-row). Row g: {c0,c1} of both tiles;
        // row g+8: {c2,c3}. Groups of 4 lanes share a row -> shfl 1,2.
        float r1[4] = { cqk[0][0] * 0.25f, cqk[0][1] * 0.25f,
                        cqk[1][0] * 0.25f, cqk[1][1] * 0.25f };
        float r2[4] = { cqk[0][2] * 0.25f, cqk[0][3] * 0.25f,
                        cqk[1][2] * 0.25f, cqk[1][3] * 0.25f };
        float mx1 = fmaxf(fmaxf(r1[0], r1[1]), fmaxf(r1[2], r1[3]));
        float mx2 = fmaxf(fmaxf(r2[0], r2[1]), fmaxf(r2[2], r2[3]));
        mx1 = fmaxf(mx1, __shfl_xor_sync(0xffffffffu, mx1, 1));
        mx1 = fmaxf(mx1, __shfl_xor_sync(0xffffffffu, mx1, 2));
        mx2 = fmaxf(mx2, __shfl_xor_sync(0xffffffffu, mx2, 1));
        mx2 = fmaxf(mx2, __shfl_xor_sync(0xffffffffu, mx2, 2));
        float s1 = 0.f, s2 = 0.f;
#pragma unroll
        for (int b = 0; b < 4; b++) { r1[b] = __expf(r1[b] - mx1); s1 += r1[b]; }
#pragma unroll
        for (int b = 0; b < 4; b++) { r2[b] = __expf(r2[b] - mx2); s2 += r2[b]; }
        s1 += __shfl_xor_sync(0xffffffffu, s1, 1);
        s1 += __shfl_xor_sync(0xffffffffu, s1, 2);
        s2 += __shfl_xor_sync(0xffffffffu, s2, 1);
        s2 += __shfl_xor_sync(0xffffffffu, s2, 2);
        float i1 = 1.f / s1, i2 = 1.f / s2;
#pragma unroll
        for (int b = 0; b < 4; b++) { r1[b] *= i1; r2[b] *= i2; }

        // att -> A-frag (m=a, k=b): a0={r1[0],r1[1]} a1={r2[0],r2[1]}
        //                           a2={r1[2],r1[3]} a3={r2[2],r2[3]}
        __half h0a, l0a, h0b, l0b, h1a, l1a, h1b, l1b;
        __half h2a, l2a, h2b, l2b, h3a, l3a, h3b, l3b;
        splith(r1[0], h0a, l0a); splith(r1[1], h0b, l0b);
        splith(r2[0], h1a, l1a); splith(r2[1], h1b, l1b);
        splith(r1[2], h2a, l2a); splith(r1[3], h2b, l2b);
        splith(r2[2], h3a, l3a); splith(r2[3], h3b, l3b);
        unsigned ath[4] = { h2pack(h0a, h0b), h2pack(h1a, h1b),
                            h2pack(h2a, h2b), h2pack(h3a, h3b) };
        unsigned atl[4] = { h2pack(l0a, l0b), h2pack(l1a, l1b),
                            h2pack(l2a, l2b), h2pack(l3a, l3b) };

        // AV: msg[a][h] += att @ V, 3 terms per h-tile (k=b is single tile)
#pragma unroll
        for (int ht = 0; ht < 4; ht++) {
            mma16(macc[ht], ath[0], ath[1], ath[2], ath[3], vh[ht][0], vh[ht][1]);
            mma16(macc[ht], atl[0], atl[1], atl[2], atl[3], vh[ht][0], vh[ht][1]);
            mma16(macc[ht], ath[0], ath[1], ath[2], ath[3], vl[ht][0], vl[ht][1]);
        }
    }

    // write agg[i][h*16+a], split hi/lo. c-frag: (a=g, h=ht*8+2t[+1]), rows +8.
    __half* oph = Omh + (size_t)i * QKV;
    __half* opl = Oml + (size_t)i * QKV;
#pragma unroll
    for (int ht = 0; ht < 4; ht++) {
        int h0 = ht * 8 + 2 * t;
        __half hv, lv;
        splith(macc[ht][0], hv, lv);
        oph[h0 * 16 + g] = hv;        opl[h0 * 16 + g] = lv;
        splith(macc[ht][1], hv, lv);
        oph[(h0 + 1) * 16 + g] = hv;  opl[(h0 + 1) * 16 + g] = lv;
        splith(macc[ht][2], hv, lv);
        oph[h0 * 16 + g + 8] = hv;    opl[h0 * 16 + g + 8] = lv;
        splith(macc[ht][3], hv, lv);
        oph[(h0 + 1) * 16 + g + 8] = hv; opl[(h0 + 1) * 16 + g + 8] = lv;
    }
}

// ---------------- host launcher ----------------
extern "C" void kernel_launch(void* const* d_in, const int* in_sizes, int n_in,
                              void* d_out, int out_size)
{
    const float* x       = (const float*)d_in[0];
    const void*  eidx    =               d_in[1];
    const float* W_embed = (const float*)d_in[2];
    const float* Wq      = (const float*)d_in[3];
    const float* Wk      = (const float*)d_in[4];
    const float* Wv      = (const float*)d_in[5];
    const float* Wo      = (const float*)d_in[6];
    const float* bo      = (const float*)d_in[7];
    const float* Wm      = (const float*)d_in[8];
    const float* bm      = (const float*)d_in[9];
    const float* g_ln    = (const float*)d_in[10];
    const float* b_ln    = (const float*)d_in[11];
    const float* g_mlp   = (const float*)d_in[12];
    const float* b_mlp   = (const float*)d_in[13];
    float* out = (float*)d_out;

    __half *pxh, *pxl, *pWeh, *pWel, *pWfh, *pWfl, *pWoh, *pWol, *pWmh, *pWml;
    __half *phh, *phl, *pt1h, *pt1l, *pAh, *pAl, *pQh, *pQl;
    float *ph, *pt0, *pt1;
    cudaGetSymbolAddress((void**)&pxh,  g_xh);
    cudaGetSymbolAddress((void**)&pxl,  g_xl);
    cudaGetSymbolAddress((void**)&pWeh, g_Weh);
    cudaGetSymbolAddress((void**)&pWel, g_Wel);
    cudaGetSymbolAddress((void**)&pWfh, g_Wfh);
    cudaGetSymbolAddress((void**)&pWfl, g_Wfl);
    cudaGetSymbolAddress((void**)&pWoh, g_Woh);
    cudaGetSymbolAddress((void**)&pWol, g_Wol);
    cudaGetSymbolAddress((void**)&pWmh, g_Wmh);
    cudaGetSymbolAddress((void**)&pWml, g_Wml);
    cudaGetSymbolAddress((void**)&ph,   g_h);
    cudaGetSymbolAddress((void**)&phh,  g_hh);
    cudaGetSymbolAddress((void**)&phl,  g_hl);
    cudaGetSymbolAddress((void**)&pt0,  g_t0);
    cudaGetSymbolAddress((void**)&pt1,  g_t1);
    cudaGetSymbolAddress((void**)&pt1h, g_t1h);
    cudaGetSymbolAddress((void**)&pt1l, g_t1l);
    cudaGetSymbolAddress((void**)&pQh,  g_QKVh);
    cudaGetSymbolAddress((void**)&pQl,  g_QKVl);
    cudaGetSymbolAddress((void**)&pAh,  g_ath);
    cudaGetSymbolAddress((void**)&pAl,  g_atl);

    // launches 1-3: splits (x unscaled; all weights x32)
    split_pad_kernel<<<NNODE, 256>>>(x, pxh, pxl, FIN, KPAD, 1.0f);
    split_pad_kernel<<<DMODEL, 256>>>(W_embed, pWeh, pWel, FIN, KPAD, WSCALE);
    splitw_kernel<<<(WTOT + 255) / 256, 256>>>(Wq, Wk, Wv, Wo, Wm);

    // launch 4: embedding GEMM (profiler captures launch #4)
    const dim3 gEmb(DMODEL / BN, (NNODE + 127) / 128);
    gemm3h<<<gEmb, 256>>>(pxh, pxl, pWeh, pWel, nullptr, nullptr,
                          ph, phh, phl, NNODE, DMODEL, KPAD, 0);

    // CSR build
    detect_kernel<<<1, 32>>>((const unsigned int*)eidx);
    zero_cnt_kernel<<<(NNODE + 255) / 256, 256>>>();
    hist_kernel<<<(NEDGE + 255) / 256, 256>>>(eidx);
    scan_kernel<<<1, 1024>>>();
    scatter_kernel<<<(NEDGE + 255) / 256, 256>>>(eidx);

    const dim3 gF(QKV3 / BN,   (NNODE + 127) / 128);
    const dim3 gD(DMODEL / BN, (NNODE + 127) / 128);

    for (int l = 0; l < NLAYER; l++) {
        // fused QKV -> remapped fp16 hi/lo only (no fp32 output)
        gemm3h<<<gF, 256>>>(phh, phl,
                            pWfh + (size_t)l * QKV3 * DMODEL,
                            pWfl + (size_t)l * QKV3 * DMODEL,
                            nullptr, nullptr, nullptr, pQh, pQl,
                            NNODE, QKV3, DMODEL, 1);

        attn_mma_kernel<<<(NNODE + 3) / 4, 128>>>(pQh, pQl, pAh, pAl);

        // h1x = h + attn @ Wo^T + bo
        gemm3h<<<gD, 256>>>(pAh, pAl,
                            pWoh + (size_t)l * DMODEL * QKV,
                            pWol + (size_t)l * DMODEL * QKV,
                            bo + (size_t)l * DMODEL, ph,
                            pt0, nullptr, nullptr,
                            NNODE, DMODEL, QKV, 0);
        ln_kernel<<<(NNODE * 32 + 255) / 256, 256>>>(pt0, g_ln + (size_t)l * DMODEL,
                                                     b_ln + (size_t)l * DMODEL,
                                                     pt1, pt1h, pt1l);

        // h2 = h1 + h1 @ Wm^T + bm
        gemm3h<<<gD, 256>>>(pt1h, pt1l,
                            pWmh + (size_t)l * DMODEL * DMODEL,
                            pWml + (size_t)l * DMODEL * DMODEL,
                            bm + (size_t)l * DMODEL, pt1,
                            pt0, nullptr, nullptr,
                            NNODE, DMODEL, DMODEL, 0);
        bool last = (l == NLAYER - 1);
        ln_kernel<<<(NNODE * 32 + 255) / 256, 256>>>(pt0, g_mlp + (size_t)l * DMODEL,
                                                     b_mlp + (size_t)l * DMODEL,
                                                     last ? out : ph,
                                                     last ? nullptr : phh,
                                                     last ? nullptr : phl);
    }
}

// round 14
// speedup vs baseline: 1.2458x; 1.2458x over previous
#include <cuda_runtime.h>
#include <cuda_fp16.h>

// Problem constants
#define NNODE   10000
#define NEDGE   160000
#define FIN     3703
#define KPAD    3712     // FIN padded to multiple of 16
#define DMODEL  256
#define NHEAD   32
#define DK      16
#define QKV     512
#define QKV3    1536
#define NLAYER  7

// GEMM tiling (R10-proven skeleton)
#define BM 128
#define BN 128
#define SROWH 24
#define TILE_H (128*SROWH)
#define STAGE_H (4*TILE_H)
#define WSCALE 32.0f
#define WINV   0.03125f

#define SQ1 (QKV*DMODEL)
#define SQT (NLAYER*SQ1)
#define SOT (NLAYER*DMODEL*QKV)
#define SMT (NLAYER*DMODEL*DMODEL)
#define WTOT (3*SQT + SOT + SMT)

// ---------------- device scratch ----------------
__device__ __half g_xh [NNODE * KPAD];
__device__ __half g_xl [NNODE * KPAD];
__device__ __half g_Weh[DMODEL * KPAD];
__device__ __half g_Wel[DMODEL * KPAD];
__device__ __half g_Wfh[NLAYER * QKV3 * DMODEL];   // fused, ROW-PERMUTED Wq|Wk|Wv
__device__ __half g_Wfl[NLAYER * QKV3 * DMODEL];
__device__ __half g_Woh[SOT];
__device__ __half g_Wol[SOT];
__device__ __half g_Wmh[SMT];
__device__ __half g_Wml[SMT];

__device__ float  g_h  [NNODE * DMODEL];
__device__ __half g_hh [NNODE * DMODEL];
__device__ __half g_hl [NNODE * DMODEL];
__device__ float  g_t0 [NNODE * DMODEL];
__device__ float  g_t1 [NNODE * DMODEL];
__device__ __half g_t1h[NNODE * DMODEL];
__device__ __half g_t1l[NNODE * DMODEL];
__device__ __half g_QKVh[NNODE * QKV3];   // Q[a*32+h] | K[b*32+h] | V[h*16+b]
__device__ __half g_QKVl[NNODE * QKV3];
__device__ __half g_ath[NNODE * QKV];
__device__ __half g_atl[NNODE * QKV];

__device__ int g_cnt [NNODE];
__device__ int g_off [NNODE + 1];
__device__ int g_cur [NNODE];
__device__ int g_esrc[NEDGE];
__device__ int g_is64;

// ---------------- fp16 two-term split ----------------
__device__ __forceinline__ void splith(float x, __half& hi, __half& lo) {
    hi = __float2half_rn(x);
    lo = __float2half_rn(x - __half2float(hi));
}
__device__ __forceinline__ unsigned h2pack(__half a, __half b) {
    __half2 t = __halves2half2(a, b);
    return *(unsigned*)&t;
}

// ---------------- split kernels ----------------
__global__ void split_pad_kernel(const float* __restrict__ src,
                                 __half* __restrict__ hi, __half* __restrict__ lo,
                                 int cols, int colspad, float scale) {
    int row = blockIdx.x;
    const float* s = src + (size_t)row * cols;
    __half* ph = hi + (size_t)row * colspad;
    __half* pl = lo + (size_t)row * colspad;
    for (int c = threadIdx.x; c < cols; c += blockDim.x) {
        __half h, l;
        splith(s[c] * scale, h, l);
        ph[c] = h; pl[c] = l;
    }
}

// Weight split with fused-QKV row permutation so the QKV GEMM's natural
// output is already in attention fragment layout:
//   Wq row n=h*16+dk  -> fused row dk*32+h
//   Wk row n=h*16+dk  -> fused row 512 + dk*32+h
//   Wv row n          -> fused row 1024 + n        (V stays [h][dk])
__global__ void splitw_kernel(const float* __restrict__ Wq, const float* __restrict__ Wk,
                              const float* __restrict__ Wv, const float* __restrict__ Wo,
                              const float* __restrict__ Wm) {
    int idx = blockIdx.x * blockDim.x + threadIdx.x;
    if (idx >= WTOT) return;
    float v; __half *dh, *dl;
    if (idx < 3 * SQT) {
        int region = idx / SQT;            // 0=Q 1=K 2=V
        int i2 = idx - region * SQT;
        int l = i2 / SQ1, r = i2 % SQ1;
        int n = r >> 8, dc = r & 255;      // row, col (DMODEL=256)
        v = (region == 0) ? Wq[i2] : (region == 1) ? Wk[i2] : Wv[i2];
        int npr;
        if (region == 2) npr = 1024 + n;
        else {
            int head = n >> 4, dk = n & 15;
            npr = region * 512 + dk * 32 + head;
        }
        size_t d = (size_t)l * (3 * SQ1) + (size_t)npr * DMODEL + dc;
        dh = g_Wfh + d; dl = g_Wfl + d;
    } else if (idx < 3 * SQT + SOT) {
        int i2 = idx - 3 * SQT;
        v = Wo[i2]; dh = g_Woh + i2; dl = g_Wol + i2;
    } else {
        int i2 = idx - 3 * SQT - SOT;
        v = Wm[i2]; dh = g_Wmh + i2; dl = g_Wml + i2;
    }
    __half h, l;
    splith(v * WSCALE, h, l);
    *dh = h; *dl = l;
}

// ---------------- edge index dtype detection + CSR ----------------
__global__ void detect_kernel(const unsigned int* __restrict__ w) {
    if (threadIdx.x == 0 && blockIdx.x == 0) {
        int is64 = 1;
        for (int i = 1; i < 128; i += 2)
            if (w[i] != 0u) { is64 = 0; break; }
        g_is64 = is64;
    }
}

__device__ __forceinline__ int read_edge(const void* eidx, int pos) {
    if (g_is64) return (int)(((const long long*)eidx)[pos]);
    return ((const int*)eidx)[pos];
}

__global__ void zero_cnt_kernel() {
    int i = blockIdx.x * blockDim.x + threadIdx.x;
    if (i < NNODE) g_cnt[i] = 0;
}

__global__ void hist_kernel(const void* __restrict__ eidx) {
    int e = blockIdx.x * blockDim.x + threadIdx.x;
    if (e >= NEDGE) return;
    atomicAdd(&g_cnt[read_edge(eidx, NEDGE + e)], 1);
}

__global__ void scan_kernel() {
    __shared__ int ss[1024];
    int t = threadIdx.x;
    const int CH = (NNODE + 1023) / 1024;
    int b = t * CH;
    int e = b + CH; if (e > NNODE) e = NNODE;
    int s = 0;
    for (int i = b; i < e; i++) s += g_cnt[i];
    ss[t] = s;
    __syncthreads();
    for (int o = 1; o < 1024; o <<= 1) {
        int v = (t >= o) ? ss[t - o] : 0;
        __syncthreads();
        ss[t] += v;
        __syncthreads();
    }
    int base = ss[t] - s;
    for (int i = b; i < e; i++) {
        g_off[i] = base;
        g_cur[i] = base;
        base += g_cnt[i];
    }
    if (t == 1023) g_off[NNODE] = ss[1023];
}

__global__ void scatter_kernel(const void* __restrict__ eidx) {
    int e = blockIdx.x * blockDim.x + threadIdx.x;
    if (e >= NEDGE) return;
    int d = read_edge(eidx, NEDGE + e);
    int s = read_edge(eidx, e);
    g_esrc[atomicAdd(&g_cur[d], 1)] = s;
}

// ---------------- fp16 mma + ldmatrix helpers ----------------
__device__ __forceinline__ void mma16(float* c,
                                      unsigned a0, unsigned a1, unsigned a2, unsigned a3,
                                      unsigned b0, unsigned b1) {
    asm volatile(
        "mma.sync.aligned.m16n8k16.row.col.f32.f16.f16.f32 "
        "{%0,%1,%2,%3}, {%4,%5,%6,%7}, {%8,%9}, {%0,%1,%2,%3};\n"
        : "+f"(c[0]), "+f"(c[1]), "+f"(c[2]), "+f"(c[3])
        : "r"(a0), "r"(a1), "r"(a2), "r"(a3), "r"(b0), "r"(b1));
}

__device__ __forceinline__ void ldsm4(unsigned& r0, unsigned& r1,
                                      unsigned& r2, unsigned& r3, unsigned addr) {
    asm volatile(
        "ldmatrix.sync.aligned.m8n8.x4.shared.b16 {%0,%1,%2,%3}, [%4];\n"
        : "=r"(r0), "=r"(r1), "=r"(r2), "=r"(r3) : "r"(addr));
}

// ---------------- GEMM: C = addend + bias + (A @ B^T)/32  (3xFP16) --------
__global__ __launch_bounds__(256, 2)
void gemm3h(const __half* __restrict__ Ah, const __half* __restrict__ Al,
            const __half* __restrict__ Bh, const __half* __restrict__ Bl,
            const float* __restrict__ bias, const float* __restrict__ addend,
            float* __restrict__ C, __half* __restrict__ Ch, __half* __restrict__ Cl,
            int M, int Nn, int K)
{
    __shared__ __align__(16) __half smem[2][STAGE_H];   // 48 KB

    const int tid = threadIdx.x;
    const int m0 = blockIdx.y * BM;
    const int n0 = blockIdx.x * BN;
    const int lane = tid & 31, wid = tid >> 5;
    const int wm = wid & 1, wn = wid >> 1;

    const int nkt = K >> 4;

    float acc[4][4][4] = {};

    const int lr = tid >> 1;
    const int lc = (tid & 1) * 8;
    const int mA = (m0 + lr < M) ? (m0 + lr) : (M - 1);
    const int nB = n0 + lr;

    const int a_row = ((lane >> 3) & 1) * 8 + (lane & 7);
    const int a_col = ((lane >> 4) & 1) * 8;
    const unsigned aoffB = (unsigned)((a_row * SROWH + a_col) * 2);
    const int b_row = ((lane >> 4) & 1) * 8 + (lane & 7);
    const int b_col = ((lane >> 3) & 1) * 8;
    const unsigned boffB = (unsigned)((b_row * SROWH + b_col) * 2);

    unsigned sbase[2];
    sbase[0] = (unsigned)__cvta_generic_to_shared(&smem[0][0]);
    sbase[1] = (unsigned)__cvta_generic_to_shared(&smem[1][0]);

    uint4 vah, val, vbh, vbl;

#define LOADT(t_) do {                                                         \
        const int _k16 = (t_) << 4;                                           \
        vah = *(const uint4*)(Ah + (size_t)mA * K + _k16 + lc);                \
        val = *(const uint4*)(Al + (size_t)mA * K + _k16 + lc);                \
        vbh = *(const uint4*)(Bh + (size_t)nB * K + _k16 + lc);                \
        vbl = *(const uint4*)(Bl + (size_t)nB * K + _k16 + lc);                \
    } while (0)

#define STORET(st_) do {                                                       \
        __half* _s = smem[st_];                                                \
        *(uint4*)&_s[             lr * SROWH + lc] = vah;                      \
        *(uint4*)&_s[TILE_H     + lr * SROWH + lc] = val;                      \
        *(uint4*)&_s[2 * TILE_H + lr * SROWH + lc] = vbh;                      \
        *(uint4*)&_s[3 * TILE_H + lr * SROWH + lc] = vbl;                      \
    } while (0)

    LOADT(0);
    STORET(0);
    __syncthreads();

    for (int t = 0; t < nkt; t++) {
        const int cur = t & 1;
        if (t + 1 < nkt) LOADT(t + 1);

        const unsigned sb = sbase[cur];

        unsigned bh0[4], bh1[4], bl0[4], bl1[4];
#pragma unroll
        for (int jp = 0; jp < 2; jp++) {
            unsigned bd = sb + (unsigned)((2 * TILE_H + (wn * 32 + jp * 16) * SROWH) * 2) + boffB;
            ldsm4(bh0[2 * jp], bh1[2 * jp], bh0[2 * jp + 1], bh1[2 * jp + 1], bd);
            ldsm4(bl0[2 * jp], bl1[2 * jp], bl0[2 * jp + 1], bl1[2 * jp + 1],
                  bd + (unsigned)(TILE_H * 2));
        }
#pragma unroll
        for (int i = 0; i < 4; i++) {
            unsigned ad = sb + (unsigned)(((wm * 64 + i * 16) * SROWH) * 2) + aoffB;
            unsigned ah0, ah1, ah2, ah3, al0, al1, al2, al3;
            ldsm4(ah0, ah1, ah2, ah3, ad);
            ldsm4(al0, al1, al2, al3, ad + (unsigned)(TILE_H * 2));
#pragma unroll
            for (int j = 0; j < 4; j++) {
                mma16(acc[i][j], ah0, ah1, ah2, ah3, bh0[j], bh1[j]);
                mma16(acc[i][j], al0, al1, al2, al3, bh0[j], bh1[j]);
                mma16(acc[i][j], ah0, ah1, ah2, ah3, bl0[j], bl1[j]);
            }
        }

        if (t + 1 < nkt) STORET(cur ^ 1);
        __syncthreads();
    }
#undef LOADT
#undef STORET

    // epilogue: rescale by 1/32 (weights pre-scaled x32)
#pragma unroll
    for (int i = 0; i < 4; i++) {
        int mrow = m0 + wm * 64 + i * 16 + (lane >> 2);
#pragma unroll
        for (int j = 0; j < 4; j++) {
            int ncol = n0 + wn * 32 + j * 8 + (lane & 3) * 2;
            float bv0 = 0.f, bv1 = 0.f;
            if (bias) { bv0 = bias[ncol]; bv1 = bias[ncol + 1]; }
#pragma unroll
            for (int r = 0; r < 2; r++) {
                int mr = mrow + r * 8;
                if (mr >= M) continue;
                size_t idx = (size_t)mr * Nn + ncol;
                float v0 = acc[i][j][r * 2 + 0] * WINV + bv0;
                float v1 = acc[i][j][r * 2 + 1] * WINV + bv1;
                if (addend) { v0 += addend[idx]; v1 += addend[idx + 1]; }
                if (C) {
                    C[idx]     = v0;
                    C[idx + 1] = v1;
                }
                if (Ch) {
                    __half h0, l0, h1, l1;
                    splith(v0, h0, l0);
                    splith(v1, h1, l1);
                    Ch[idx] = h0;      Cl[idx] = l0;
                    Ch[idx + 1] = h1;  Cl[idx + 1] = l1;
                }
            }
        }
    }
}

// ---------------- LayerNorm (warp per row) with optional split outputs ----
__global__ __launch_bounds__(256)
void ln_kernel(const float* __restrict__ X, const float* __restrict__ gamma,
               const float* __restrict__ beta, float* __restrict__ Y,
               __half* __restrict__ Yh, __half* __restrict__ Yl)
{
    int idx = blockIdx.x * blockDim.x + threadIdx.x;
    int row = idx >> 5;
    int lane = idx & 31;
    if (row >= NNODE) return;

    const float4* xp = (const float4*)(X + (size_t)row * DMODEL);
    float4 v0 = xp[lane];
    float4 v1 = xp[lane + 32];

    float s = v0.x + v0.y + v0.z + v0.w + v1.x + v1.y + v1.z + v1.w;
#pragma unroll
    for (int o = 16; o; o >>= 1) s += __shfl_xor_sync(0xffffffffu, s, o);
    float mean = s * (1.f / 256.f);

    float d, q = 0.f;
    d = v0.x - mean; q += d * d;  d = v0.y - mean; q += d * d;
    d = v0.z - mean; q += d * d;  d = v0.w - mean; q += d * d;
    d = v1.x - mean; q += d * d;  d = v1.y - mean; q += d * d;
    d = v1.z - mean; q += d * d;  d = v1.w - mean; q += d * d;
#pragma unroll
    for (int o = 16; o; o >>= 1) q += __shfl_xor_sync(0xffffffffu, q, o);
    float inv = rsqrtf(q * (1.f / 256.f) + 1e-5f);

    const float4* gp = (const float4*)gamma;
    const float4* bp = (const float4*)beta;
    float4 g0 = gp[lane], g1 = gp[lane + 32];
    float4 b0 = bp[lane], b1 = bp[lane + 32];

    float o0[4], o1[4];
    o0[0] = (v0.x - mean) * inv * g0.x + b0.x;
    o0[1] = (v0.y - mean) * inv * g0.y + b0.y;
    o0[2] = (v0.z - mean) * inv * g0.z + b0.z;
    o0[3] = (v0.w - mean) * inv * g0.w + b0.w;
    o1[0] = (v1.x - mean) * inv * g1.x + b1.x;
    o1[1] = (v1.y - mean) * inv * g1.y + b1.y;
    o1[2] = (v1.z - mean) * inv * g1.z + b1.z;
    o1[3] = (v1.w - mean) * inv * g1.w + b1.w;

    float4* yp = (float4*)(Y + (size_t)row * DMODEL);
    yp[lane]      = make_float4(o0[0], o0[1], o0[2], o0[3]);
    yp[lane + 32] = make_float4(o1[0], o1[1], o1[2], o1[3]);

    if (Yh) {
        __half hbuf0[4], lbuf0[4], hbuf1[4], lbuf1[4];
#pragma unroll
        for (int k = 0; k < 4; k++) {
            splith(o0[k], hbuf0[k], lbuf0[k]);
            splith(o1[k], hbuf1[k], lbuf1[k]);
        }
        uint2* hp = (uint2*)(Yh + (size_t)row * DMODEL);
        uint2* lp = (uint2*)(Yl + (size_t)row * DMODEL);
        hp[lane]      = *(uint2*)hbuf0;
        hp[lane + 32] = *(uint2*)hbuf1;
        lp[lane]      = *(uint2*)lbuf0;
        lp[lane + 32] = *(uint2*)lbuf1;
    }
}

// ---------------- edge attention: warp/node MMA + register prefetch ------
// Layouts (halves): Q +0 [a*32+h], K +512 [b*32+h], V +1024 [h*16+b].
// Fragment mappings identical to R13 (verified correct).
#define LDFR(J, KH, KL, VH, VL) do {                                           \
        const __half* _kH = QKVh + (size_t)(J) * QKV3 + 512;                   \
        const __half* _kL = QKVl + (size_t)(J) * QKV3 + 512;                   \
        const __half* _vH = QKVh + (size_t)(J) * QKV3 + 1024;                  \
        const __half* _vL = QKVl + (size_t)(J) * QKV3 + 1024;                  \
        _Pragma("unroll")                                                      \
        for (int _nt = 0; _nt < 2; _nt++)                                      \
        _Pragma("unroll")                                                      \
        for (int _kt = 0; _kt < 2; _kt++) {                                    \
            int _off = (_nt * 8 + g) * 32 + _kt * 16 + 2 * t;                  \
            KH[_nt * 4 + _kt * 2 + 0] = *(const unsigned*)(_kH + _off);        \
            KH[_nt * 4 + _kt * 2 + 1] = *(const unsigned*)(_kH + _off + 8);    \
            KL[_nt * 4 + _kt * 2 + 0] = *(const unsigned*)(_kL + _off);        \
            KL[_nt * 4 + _kt * 2 + 1] = *(const unsigned*)(_kL + _off + 8);    \
        }                                                                      \
        _Pragma("unroll")                                                      \
        for (int _ht = 0; _ht < 4; _ht++) {                                    \
            int _off = (_ht * 8 + g) * 16 + 2 * t;                             \
            VH[_ht * 2 + 0] = *(const unsigned*)(_vH + _off);                  \
            VH[_ht * 2 + 1] = *(const unsigned*)(_vH + _off + 8);              \
            VL[_ht * 2 + 0] = *(const unsigned*)(_vL + _off);                  \
            VL[_ht * 2 + 1] = *(const unsigned*)(_vL + _off + 8);              \
        }                                                                      \
    } while (0)

__global__ __launch_bounds__(128)
void attn_mma_kernel(const __half* __restrict__ QKVh, const __half* __restrict__ QKVl,
                     __half* __restrict__ Omh, __half* __restrict__ Oml)
{
    const int warp = (blockIdx.x * blockDim.x + threadIdx.x) >> 5;
    const int lane = threadIdx.x & 31;
    if (warp >= NNODE) return;
    const int i = warp;
    const int g = lane >> 2;
    const int t = lane & 3;

    const __half* qH = QKVh + (size_t)i * QKV3;
    const __half* qL = QKVl + (size_t)i * QKV3;

    unsigned qh[2][4], ql[2][4];
#pragma unroll
    for (int kt = 0; kt < 2; kt++) {
        int k0 = kt * 16 + 2 * t;
        qh[kt][0] = *(const unsigned*)(qH + g * 32 + k0);
        qh[kt][1] = *(const unsigned*)(qH + (g + 8) * 32 + k0);
        qh[kt][2] = *(const unsigned*)(qH + g * 32 + k0 + 8);
        qh[kt][3] = *(const unsigned*)(qH + (g + 8) * 32 + k0 + 8);
        ql[kt][0] = *(const unsigned*)(qL + g * 32 + k0);
        ql[kt][1] = *(const unsigned*)(qL + (g + 8) * 32 + k0);
        ql[kt][2] = *(const unsigned*)(qL + g * 32 + k0 + 8);
        ql[kt][3] = *(const unsigned*)(qL + (g + 8) * 32 + k0 + 8);
    }

    float macc[4][4] = {};

    const int e0 = g_off[i];
    const int e1 = g_off[i + 1];

    unsigned kh[8], kl[8], vh8[8], vl8[8];
    if (e0 < e1) LDFR(g_esrc[e0], kh, kl, vh8, vl8);

    for (int e = e0; e < e1; e++) {
        unsigned nkh[8], nkl[8], nvh[8], nvl[8];
        const bool more = (e + 1 < e1);
        if (more) LDFR(g_esrc[e + 1], nkh, nkl, nvh, nvl);

        // QK: alpha[a][b]
        float cqk[2][4] = {};
#pragma unroll
        for (int nt = 0; nt < 2; nt++) {
#pragma unroll
            for (int kt = 0; kt < 2; kt++) {
                unsigned b0h = kh[nt * 4 + kt * 2], b1h = kh[nt * 4 + kt * 2 + 1];
                unsigned b0l = kl[nt * 4 + kt * 2], b1l = kl[nt * 4 + kt * 2 + 1];
                mma16(cqk[nt], qh[kt][0], qh[kt][1], qh[kt][2], qh[kt][3], b0h, b1h);
                mma16(cqk[nt], ql[kt][0], ql[kt][1], ql[kt][2], ql[kt][3], b0h, b1h);
                mma16(cqk[nt], qh[kt][0], qh[kt][1], qh[kt][2], qh[kt][3], b0l, b1l);
            }
        }

        // softmax over b (rows g and g+8; 4-lane groups share a row)
        float r1[4] = { cqk[0][0] * 0.25f, cqk[0][1] * 0.25f,
                        cqk[1][0] * 0.25f, cqk[1][1] * 0.25f };
        float r2[4] = { cqk[0][2] * 0.25f, cqk[0][3] * 0.25f,
                        cqk[1][2] * 0.25f, cqk[1][3] * 0.25f };
        float mx1 = fmaxf(fmaxf(r1[0], r1[1]), fmaxf(r1[2], r1[3]));
        float mx2 = fmaxf(fmaxf(r2[0], r2[1]), fmaxf(r2[2], r2[3]));
        mx1 = fmaxf(mx1, __shfl_xor_sync(0xffffffffu, mx1, 1));
        mx1 = fmaxf(mx1, __shfl_xor_sync(0xffffffffu, mx1, 2));
        mx2 = fmaxf(mx2, __shfl_xor_sync(0xffffffffu, mx2, 1));
        mx2 = fmaxf(mx2, __shfl_xor_sync(0xffffffffu, mx2, 2));
        float s1 = 0.f, s2 = 0.f;
#pragma unroll
        for (int b = 0; b < 4; b++) { r1[b] = __expf(r1[b] - mx1); s1 += r1[b]; }
#pragma unroll
        for (int b = 0; b < 4; b++) { r2[b] = __expf(r2[b] - mx2); s2 += r2[b]; }
        s1 += __shfl_xor_sync(0xffffffffu, s1, 1);
        s1 += __shfl_xor_sync(0xffffffffu, s1, 2);
        s2 += __shfl_xor_sync(0xffffffffu, s2, 1);
        s2 += __shfl_xor_sync(0xffffffffu, s2, 2);
        float i1 = 1.f / s1, i2 = 1.f / s2;
#pragma unroll
        for (int b = 0; b < 4; b++) { r1[b] *= i1; r2[b] *= i2; }

        // att -> A-frag hi/lo
        __half h0a, l0a, h0b, l0b, h1a, l1a, h1b, l1b;
        __half h2a, l2a, h2b, l2b, h3a, l3a, h3b, l3b;
        splith(r1[0], h0a, l0a); splith(r1[1], h0b, l0b);
        splith(r2[0], h1a, l1a); splith(r2[1], h1b, l1b);
        splith(r1[2], h2a, l2a); splith(r1[3], h2b, l2b);
        splith(r2[2], h3a, l3a); splith(r2[3], h3b, l3b);
        unsigned ath[4] = { h2pack(h0a, h0b), h2pack(h1a, h1b),
                            h2pack(h2a, h2b), h2pack(h3a, h3b) };
        unsigned atl[4] = { h2pack(l0a, l0b), h2pack(l1a, l1b),
                            h2pack(l2a, l2b), h2pack(l3a, l3b) };

        // AV: msg[a][h] += att @ V
#pragma unroll
        for (int ht = 0; ht < 4; ht++) {
            unsigned v0h = vh8[ht * 2], v1h = vh8[ht * 2 + 1];
            unsigned v0l = vl8[ht * 2], v1l = vl8[ht * 2 + 1];
            mma16(macc[ht], ath[0], ath[1], ath[2], ath[3], v0h, v1h);
            mma16(macc[ht], atl[0], atl[1], atl[2], atl[3], v0h, v1h);
            mma16(macc[ht], ath[0], ath[1], ath[2], ath[3], v0l, v1l);
        }

        if (more) {
#pragma unroll
            for (int p = 0; p < 8; p++) {
                kh[p] = nkh[p]; kl[p] = nkl[p];
                vh8[p] = nvh[p]; vl8[p] = nvl[p];
            }
        }
    }

    // write agg[i][h*16+a], split hi/lo
    __half* oph = Omh + (size_t)i * QKV;
    __half* opl = Oml + (size_t)i * QKV;
#pragma unroll
    for (int ht = 0; ht < 4; ht++) {
        int h0 = ht * 8 + 2 * t;
        __half hv, lv;
        splith(macc[ht][0], hv, lv);
        oph[h0 * 16 + g] = hv;        opl[h0 * 16 + g] = lv;
        splith(macc[ht][1], hv, lv);
        oph[(h0 + 1) * 16 + g] = hv;  opl[(h0 + 1) * 16 + g] = lv;
        splith(macc[ht][2], hv, lv);
        oph[h0 * 16 + g + 8] = hv;    opl[h0 * 16 + g + 8] = lv;
        splith(macc[ht][3], hv, lv);
        oph[(h0 + 1) * 16 + g + 8] = hv; opl[(h0 + 1) * 16 + g + 8] = lv;
    }
}

// ---------------- host launcher ----------------
extern "C" void kernel_launch(void* const* d_in, const int* in_sizes, int n_in,
                              void* d_out, int out_size)
{
    const float* x       = (const float*)d_in[0];
    const void*  eidx    =               d_in[1];
    const float* W_embed = (const float*)d_in[2];
    const float* Wq      = (const float*)d_in[3];
    const float* Wk      = (const float*)d_in[4];
    const float* Wv      = (const float*)d_in[5];
    const float* Wo      = (const float*)d_in[6];
    const float* bo      = (const float*)d_in[7];
    const float* Wm      = (const float*)d_in[8];
    const float* bm      = (const float*)d_in[9];
    const float* g_ln    = (const float*)d_in[10];
    const float* b_ln    = (const float*)d_in[11];
    const float* g_mlp   = (const float*)d_in[12];
    const float* b_mlp   = (const float*)d_in[13];
    float* out = (float*)d_out;

    __half *pxh, *pxl, *pWeh, *pWel, *pWfh, *pWfl, *pWoh, *pWol, *pWmh, *pWml;
    __half *phh, *phl, *pt1h, *pt1l, *pAh, *pAl, *pQh, *pQl;
    float *ph, *pt0, *pt1;
    cudaGetSymbolAddress((void**)&pxh,  g_xh);
    cudaGetSymbolAddress((void**)&pxl,  g_xl);
    cudaGetSymbolAddress((void**)&pWeh, g_Weh);
    cudaGetSymbolAddress((void**)&pWel, g_Wel);
    cudaGetSymbolAddress((void**)&pWfh, g_Wfh);
    cudaGetSymbolAddress((void**)&pWfl, g_Wfl);
    cudaGetSymbolAddress((void**)&pWoh, g_Woh);
    cudaGetSymbolAddress((void**)&pWol, g_Wol);
    cudaGetSymbolAddress((void**)&pWmh, g_Wmh);
    cudaGetSymbolAddress((void**)&pWml, g_Wml);
    cudaGetSymbolAddress((void**)&ph,   g_h);
    cudaGetSymbolAddress((void**)&phh,  g_hh);
    cudaGetSymbolAddress((void**)&phl,  g_hl);
    cudaGetSymbolAddress((void**)&pt0,  g_t0);
    cudaGetSymbolAddress((void**)&pt1,  g_t1);
    cudaGetSymbolAddress((void**)&pt1h, g_t1h);
    cudaGetSymbolAddress((void**)&pt1l, g_t1l);
    cudaGetSymbolAddress((void**)&pQh,  g_QKVh);
    cudaGetSymbolAddress((void**)&pQl,  g_QKVl);
    cudaGetSymbolAddress((void**)&pAh,  g_ath);
    cudaGetSymbolAddress((void**)&pAl,  g_atl);

    // launches 1-3: splits (x unscaled; all weights x32; QKV rows permuted)
    split_pad_kernel<<<NNODE, 256>>>(x, pxh, pxl, FIN, KPAD, 1.0f);
    split_pad_kernel<<<DMODEL, 256>>>(W_embed, pWeh, pWel, FIN, KPAD, WSCALE);
    splitw_kernel<<<(WTOT + 255) / 256, 256>>>(Wq, Wk, Wv, Wo, Wm);

    // launch 4: embedding GEMM (profiler captures launch #4)
    const dim3 gEmb(DMODEL / BN, (NNODE + 127) / 128);
    gemm3h<<<gEmb, 256>>>(pxh, pxl, pWeh, pWel, nullptr, nullptr,
                          ph, phh, phl, NNODE, DMODEL, KPAD);

    // CSR build
    detect_kernel<<<1, 32>>>((const unsigned int*)eidx);
    zero_cnt_kernel<<<(NNODE + 255) / 256, 256>>>();
    hist_kernel<<<(NEDGE + 255) / 256, 256>>>(eidx);
    scan_kernel<<<1, 1024>>>();
    scatter_kernel<<<(NEDGE + 255) / 256, 256>>>(eidx);

    const dim3 gF(QKV3 / BN,   (NNODE + 127) / 128);
    const dim3 gD(DMODEL / BN, (NNODE + 127) / 128);

    for (int l = 0; l < NLAYER; l++) {
        // fused QKV -> fp16 hi/lo only, coalesced (weights pre-permuted)
        gemm3h<<<gF, 256>>>(phh, phl,
                            pWfh + (size_t)l * QKV3 * DMODEL,
                            pWfl + (size_t)l * QKV3 * DMODEL,
                            nullptr, nullptr, nullptr, pQh, pQl,
                            NNODE, QKV3, DMODEL);

        attn_mma_kernel<<<(NNODE + 3) / 4, 128>>>(pQh, pQl, pAh, pAl);

        // h1x = h + attn @ Wo^T + bo
        gemm3h<<<gD, 256>>>(pAh, pAl,
                            pWoh + (size_t)l * DMODEL * QKV,
                            pWol + (size_t)l * DMODEL * QKV,
                            bo + (size_t)l * DMODEL, ph,
                            pt0, nullptr, nullptr,
                            NNODE, DMODEL, QKV);
        ln_kernel<<<(NNODE * 32 + 255) / 256, 256>>>(pt0, g_ln + (size_t)l * DMODEL,
                                                     b_ln + (size_t)l * DMODEL,
                                                     pt1, pt1h, pt1l);

        // h2 = h1 + h1 @ Wm^T + bm
        gemm3h<<<gD, 256>>>(pt1h, pt1l,
                            pWmh + (size_t)l * DMODEL * DMODEL,
                            pWml + (size_t)l * DMODEL * DMODEL,
                            bm + (size_t)l * DMODEL, pt1,
                            pt0, nullptr, nullptr,
                            NNODE, DMODEL, DMODEL);
        bool last = (l == NLAYER - 1);
        ln_kernel<<<(NNODE * 32 + 255) / 256, 256>>>(pt0, g_mlp + (size_t)l * DMODEL,
                                                     b_mlp + (size_t)l * DMODEL,
                                                     last ? out : ph,
                                                     last ? nullptr : phh,
                                                     last ? nullptr : phl);
    }
}